// round 4
// baseline (speedup 1.0000x reference)
#include <cuda_runtime.h>

#define NCLS 80
#define DIM 256
#define NMAX 65536
#define EPSF 1e-7f
#define LOSSW 0.01f
#define JPW 8   // sorted j-indices per warp

// ---------------- device scratch (no allocations allowed) ----------------
__device__ float g_seg[NCLS * DIM];   // class segment sums over all 3N rows
__device__ int   g_counts[NCLS];
__device__ int   g_cursor[NCLS];
__device__ int   g_sorted[NMAX];
__device__ float g_t1[64];            // partial accumulators for term1

__device__ __forceinline__ int clampc(int c) {
    return (c < 0) ? 0 : (c >= NCLS ? NCLS - 1 : c);
}

// ---------------- fast x*ln(x) on FMA pipe (avoids MUFU bound) -----------
__device__ __forceinline__ float xlnx(float x) {
    // x >= 0. Returns x*ln(x); exact 0 at x == 0 (0 * finite = 0).
    int xi = __float_as_int(x);
    float ef = (float)(((xi >> 23) & 0xFF) - 127);
    float m  = __int_as_float((xi & 0x007FFFFF) | 0x3F800000);  // [1,2)
    if (m > 1.41421356f) { m *= 0.5f; ef += 1.0f; }             // m in [0.707,1.414]
    float t = m - 1.0f;                                         // [-0.293, 0.414]
    // ln(1+t), Taylor degree 10 (Horner). |rel err| < 2e-5 on this range.
    float r = -0.1f;
    r = fmaf(r, t,  0.11111111f);
    r = fmaf(r, t, -0.125f);
    r = fmaf(r, t,  0.14285714f);
    r = fmaf(r, t, -0.16666667f);
    r = fmaf(r, t,  0.2f);
    r = fmaf(r, t, -0.25f);
    r = fmaf(r, t,  0.33333333f);
    r = fmaf(r, t, -0.5f);
    r = fmaf(r, t,  1.0f);
    float lnm = r * t;
    float ln  = fmaf(ef, 0.69314718056f, lnm);
    return x * ln;
}

// ---------------- K0: zero scratch ----------------
__global__ void k_zero() {
    int i = blockIdx.x * blockDim.x + threadIdx.x;
    for (int k = i; k < NCLS * DIM; k += gridDim.x * blockDim.x) g_seg[k] = 0.0f;
    if (i < NCLS) g_counts[i] = 0;
    if (i < 64)   g_t1[i] = 0.0f;
}

// ---------------- K1: class histogram (smem privatized) ----------------
__global__ void k_hist(const int* __restrict__ labels, int N) {
    __shared__ int h[NCLS];
    for (int c = threadIdx.x; c < NCLS; c += blockDim.x) h[c] = 0;
    __syncthreads();
    for (int j = blockIdx.x * blockDim.x + threadIdx.x; j < N;
         j += gridDim.x * blockDim.x)
        atomicAdd(&h[clampc(labels[j])], 1);
    __syncthreads();
    for (int c = threadIdx.x; c < NCLS; c += blockDim.x)
        if (h[c]) atomicAdd(&g_counts[c], h[c]);
}

// ---------------- K2: exclusive prefix -> cursors ----------------
__global__ void k_prefix() {
    if (threadIdx.x == 0) {
        int run = 0;
        for (int c = 0; c < NCLS; c++) {
            g_cursor[c] = run;
            run += g_counts[c];
        }
    }
}

// ---------------- K3: counting-sort scatter of row indices ----------------
__global__ void k_scatter(const int* __restrict__ labels, int N) {
    for (int j = blockIdx.x * blockDim.x + threadIdx.x; j < N;
         j += gridDim.x * blockDim.x) {
        int c = clampc(labels[j]);
        int p = atomicAdd(&g_cursor[c], 1);
        if (p >= 0 && p < NMAX) g_sorted[p] = j;
    }
}

// ---------------- K4: fused single-pass main kernel ----------------
// One warp handles JPW sorted j-indices (3 rows each: clean/aug1/aug2).
// Lane owns 8 columns (two float4s). Register class-accumulators, flushed
// to g_seg via global red.add only on class change (sorted order -> rare).
__global__ void k_main(const float* __restrict__ x0, const float* __restrict__ x1,
                       const float* __restrict__ x2,
                       const int* __restrict__ labels, int N) {
    int gwarp = (blockIdx.x * blockDim.x + threadIdx.x) >> 5;
    int lane  = threadIdx.x & 31;
    int pos0  = gwarp * JPW;
    if (pos0 >= N) return;
    int pend = min(pos0 + JPW, N);

    float acc[8];
#pragma unroll
    for (int k = 0; k < 8; k++) acc[k] = 0.0f;
    int   curc = -1;
    float ic3  = 0.0f;   // 1 / (3 * count[c])
    float t1   = 0.0f;

    for (int pos = pos0; pos < pend; pos++) {
        int j = g_sorted[pos];
        int c = clampc(labels[j]);
        if (c != curc) {
            if (curc >= 0) {
#pragma unroll
                for (int k = 0; k < 4; k++) {
                    atomicAdd(&g_seg[curc * DIM + lane * 4 + k],       acc[k]);
                    atomicAdd(&g_seg[curc * DIM + 128 + lane * 4 + k], acc[4 + k]);
                    acc[k] = 0.0f;
                    acc[4 + k] = 0.0f;
                }
            }
            curc = c;
            ic3  = 1.0f / (3.0f * (float)g_counts[c]);
        }
#pragma unroll
        for (int mm = 0; mm < 3; mm++) {
            const float* base = (mm == 0) ? x0 : (mm == 1) ? x1 : x2;
            const float4* row = (const float4*)(base + (size_t)j * DIM);
            float4 a = row[lane];
            float4 b = row[32 + lane];

            float s1  = ((a.x + a.y) + (a.z + a.w)) + ((b.x + b.y) + (b.z + b.w));
            float s2  = fmaf(a.x, a.x, fmaf(a.y, a.y, fmaf(a.z, a.z, a.w * a.w)));
            s2 = fmaf(b.x, b.x, fmaf(b.y, b.y, fmaf(b.z, b.z, fmaf(b.w, b.w, s2))));
            float sxl = ((xlnx(a.x) + xlnx(a.y)) + (xlnx(a.z) + xlnx(a.w)))
                      + ((xlnx(b.x) + xlnx(b.y)) + (xlnx(b.z) + xlnx(b.w)));

#pragma unroll
            for (int o = 16; o; o >>= 1) {
                s1  += __shfl_xor_sync(0xffffffffu, s1, o);
                s2  += __shfl_xor_sync(0xffffffffu, s2, o);
                sxl += __shfl_xor_sync(0xffffffffu, sxl, o);
            }
            float denom = fmaxf(sqrtf(s2), 1e-12f);
            float w = 1.0f / denom;
            // xlogy row sum = w*(sxl - ln(denom)*s1); term1 += /counts3
            t1 += w * fmaf(-logf(denom), s1, sxl) * ic3;

            acc[0] = fmaf(a.x, w, acc[0]);
            acc[1] = fmaf(a.y, w, acc[1]);
            acc[2] = fmaf(a.z, w, acc[2]);
            acc[3] = fmaf(a.w, w, acc[3]);
            acc[4] = fmaf(b.x, w, acc[4]);
            acc[5] = fmaf(b.y, w, acc[5]);
            acc[6] = fmaf(b.z, w, acc[6]);
            acc[7] = fmaf(b.w, w, acc[7]);
        }
    }
    if (curc >= 0) {
#pragma unroll
        for (int k = 0; k < 4; k++) {
            atomicAdd(&g_seg[curc * DIM + lane * 4 + k],       acc[k]);
            atomicAdd(&g_seg[curc * DIM + 128 + lane * 4 + k], acc[4 + k]);
        }
    }
    if (lane == 0) atomicAdd(&g_t1[gwarp & 63], t1);
}

// ---------------- K5: finalize (tiny: 80*256 elements) ----------------
__global__ void k_final(float* __restrict__ out) {
    __shared__ float red[256];
    int d = threadIdx.x;
    float t2 = 0.0f;
    for (int c = 0; c < NCLS; c++) {
        int cnt = g_counts[c];
        if (cnt > 0) {
            float cnt3 = 3.0f * (float)cnt;
            float s    = g_seg[c * DIM + d];
            float mix  = s / cnt3;                 // counts3 >= 3 > 1
            float lm   = logf(fmaxf(mix, EPSF));
            t2 += s * lm / cnt3;
        }
    }
    red[d] = t2;
    __syncthreads();
    for (int o = 128; o; o >>= 1) {
        if (d < o) red[d] += red[d + o];
        __syncthreads();
    }
    if (d == 0) {
        float t1 = 0.0f;
        for (int i = 0; i < 64; i++) t1 += g_t1[i];
        float loss = (t1 - red[0]) / (float)DIM;
        out[0] = LOSSW * loss;
    }
}

// ---------------- launch ----------------
extern "C" void kernel_launch(void* const* d_in, const int* in_sizes, int n_in,
                              void* d_out, int out_size) {
    const float* x0  = (const float*)d_in[0];
    const float* x1  = (const float*)d_in[1];
    const float* x2  = (const float*)d_in[2];
    const int*   lab = (const int*)d_in[3];
    int N = in_sizes[3];
    if (N > NMAX) N = NMAX;

    k_zero<<<96, 256>>>();
    k_hist<<<128, 256>>>(lab, N);
    k_prefix<<<1, 32>>>();
    k_scatter<<<128, 256>>>(lab, N);

    int warps  = (N + JPW - 1) / JPW;
    int blocks = (warps + 7) / 8;
    k_main<<<blocks, 256>>>(x0, x1, x2, lab, N);

    k_final<<<1, 256>>>((float*)d_out);
}

// round 6
// speedup vs baseline: 1.4834x; 1.4834x over previous
#include <cuda_runtime.h>

#define NCLS 80
#define DIM 256
#define NMAX 65536
#define EPSF 1e-7f
#define LOSSW 0.01f
#define JPW 8   // sorted entries per warp

// ---------------- device scratch (no allocations allowed) ----------------
__device__ float g_seg[NCLS * DIM];   // class segment sums over all 3N rows
__device__ int   g_counts[NCLS];
__device__ int   g_cursor[NCLS];
__device__ int   g_sorted[NMAX];      // packed: (class<<20) | row_index
__device__ float g_t1[64];            // partial accumulators for term1

__device__ __forceinline__ int clampc(int c) {
    return (c < 0) ? 0 : (c >= NCLS ? NCLS - 1 : c);
}

// x*ln(x) via MUFU.LG2 — far cheaper than a polynomial at this op count.
__device__ __forceinline__ float xlnxf(float x) {
    float l = __logf(x);
    return (x > 0.0f) ? x * l : 0.0f;
}

// ---------------- K0: zero scratch ----------------
__global__ void k_zero() {
    int i = blockIdx.x * blockDim.x + threadIdx.x;
    for (int k = i; k < NCLS * DIM; k += gridDim.x * blockDim.x) g_seg[k] = 0.0f;
    if (i < NCLS) g_counts[i] = 0;
    if (i < 64)   g_t1[i] = 0.0f;
}

// ---------------- K1: histogram, block-aggregated ----------------
__global__ void k_hist(const int* __restrict__ labels, int N) {
    __shared__ int h[NCLS];
    for (int c = threadIdx.x; c < NCLS; c += blockDim.x) h[c] = 0;
    __syncthreads();
    int i = blockIdx.x * blockDim.x + threadIdx.x;
    if (i < N) atomicAdd(&h[clampc(labels[i])], 1);
    __syncthreads();
    for (int c = threadIdx.x; c < NCLS; c += blockDim.x)
        if (h[c]) atomicAdd(&g_counts[c], h[c]);
}

// ---------------- K2: exclusive prefix -> cursors ----------------
__global__ void k_prefix() {
    if (threadIdx.x == 0) {
        int run = 0;
        for (int c = 0; c < NCLS; c++) {
            g_cursor[c] = run;
            run += g_counts[c];
        }
    }
}

// ---------------- K3: counting-sort scatter, block-aggregated ----------------
// Pass 1: block histogram (smem atomics). One global atomic per (block,class)
// reserves the block's slice. Pass 2: smem-local cursor places each element.
// Global atomics drop from 64K (80 hot addrs) to ~10K -> no L2 serialization.
__global__ void k_scatter(const int* __restrict__ labels, int N) {
    __shared__ int h[NCLS];     // block count, then reused as local cursor
    __shared__ int base[NCLS];  // global base for this block's slice
    int tid = threadIdx.x;
    for (int c = tid; c < NCLS; c += blockDim.x) h[c] = 0;
    __syncthreads();
    int i = blockIdx.x * blockDim.x + tid;
    int c = -1;
    if (i < N) {
        c = clampc(labels[i]);
        atomicAdd(&h[c], 1);
    }
    __syncthreads();
    for (int cc = tid; cc < NCLS; cc += blockDim.x) {
        int cnt = h[cc];
        base[cc] = cnt ? atomicAdd(&g_cursor[cc], cnt) : 0;
        h[cc] = 0;
    }
    __syncthreads();
    if (i < N) {
        int loc = atomicAdd(&h[c], 1);
        int p = base[c] + loc;
        if (p >= 0 && p < NMAX) g_sorted[p] = (c << 20) | i;
    }
}

// ---------------- K4: fused single-pass main kernel ----------------
// One warp handles JPW sorted entries (3 rows each: clean/aug1/aug2).
// Lane owns 8 columns (two float4s). All six float4 loads for the three
// matrices are issued up front so memory latency overlaps the shfl chains.
// Register class-accumulators flushed to g_seg only on class change.
__global__ void k_main(const float* __restrict__ x0, const float* __restrict__ x1,
                       const float* __restrict__ x2, int N) {
    int gwarp = (blockIdx.x * blockDim.x + threadIdx.x) >> 5;
    int lane  = threadIdx.x & 31;
    int pos0  = gwarp * JPW;
    if (pos0 >= N) return;
    int pend = min(pos0 + JPW, N);

    float acc[8];
#pragma unroll
    for (int k = 0; k < 8; k++) acc[k] = 0.0f;
    int   curc = -1;
    float ic3  = 0.0f;   // 1 / (3 * count[c])
    float t1   = 0.0f;

    for (int pos = pos0; pos < pend; pos++) {
        int v = g_sorted[pos];
        int j = v & 0xFFFFF;
        int c = v >> 20;

        // Issue all 6 loads (3 matrices x 2 float4) before any compute.
        size_t off = (size_t)j * DIM;
        const float4* r0 = (const float4*)(x0 + off);
        const float4* r1 = (const float4*)(x1 + off);
        const float4* r2 = (const float4*)(x2 + off);
        float4 A[3], B[3];
        A[0] = r0[lane]; B[0] = r0[32 + lane];
        A[1] = r1[lane]; B[1] = r1[32 + lane];
        A[2] = r2[lane]; B[2] = r2[32 + lane];

        if (c != curc) {
            if (curc >= 0) {
#pragma unroll
                for (int k = 0; k < 4; k++) {
                    atomicAdd(&g_seg[curc * DIM + lane * 4 + k],       acc[k]);
                    atomicAdd(&g_seg[curc * DIM + 128 + lane * 4 + k], acc[4 + k]);
                    acc[k] = 0.0f;
                    acc[4 + k] = 0.0f;
                }
            }
            curc = c;
            ic3  = 1.0f / (3.0f * (float)g_counts[c]);
        }

#pragma unroll
        for (int mm = 0; mm < 3; mm++) {
            float4 a = A[mm];
            float4 b = B[mm];

            float s1  = ((a.x + a.y) + (a.z + a.w)) + ((b.x + b.y) + (b.z + b.w));
            float s2  = fmaf(a.x, a.x, fmaf(a.y, a.y, fmaf(a.z, a.z, a.w * a.w)));
            s2 = fmaf(b.x, b.x, fmaf(b.y, b.y, fmaf(b.z, b.z, fmaf(b.w, b.w, s2))));
            float sxl = ((xlnxf(a.x) + xlnxf(a.y)) + (xlnxf(a.z) + xlnxf(a.w)))
                      + ((xlnxf(b.x) + xlnxf(b.y)) + (xlnxf(b.z) + xlnxf(b.w)));

#pragma unroll
            for (int o = 16; o; o >>= 1) {
                s1  += __shfl_xor_sync(0xffffffffu, s1, o);
                s2  += __shfl_xor_sync(0xffffffffu, s2, o);
                sxl += __shfl_xor_sync(0xffffffffu, sxl, o);
            }
            float denom = fmaxf(sqrtf(s2), 1e-12f);
            float w = 1.0f / denom;
            // xlogy row sum = w*(sxl - ln(denom)*s1); term1 += /counts3
            t1 += w * fmaf(-__logf(denom), s1, sxl) * ic3;

            acc[0] = fmaf(a.x, w, acc[0]);
            acc[1] = fmaf(a.y, w, acc[1]);
            acc[2] = fmaf(a.z, w, acc[2]);
            acc[3] = fmaf(a.w, w, acc[3]);
            acc[4] = fmaf(b.x, w, acc[4]);
            acc[5] = fmaf(b.y, w, acc[5]);
            acc[6] = fmaf(b.z, w, acc[6]);
            acc[7] = fmaf(b.w, w, acc[7]);
        }
    }
    if (curc >= 0) {
#pragma unroll
        for (int k = 0; k < 4; k++) {
            atomicAdd(&g_seg[curc * DIM + lane * 4 + k],       acc[k]);
            atomicAdd(&g_seg[curc * DIM + 128 + lane * 4 + k], acc[4 + k]);
        }
    }
    if (lane == 0) atomicAdd(&g_t1[gwarp & 63], t1);
}

// ---------------- K5: finalize (tiny: 80*256 elements) ----------------
__global__ void k_final(float* __restrict__ out) {
    __shared__ float red[256];
    int d = threadIdx.x;
    float t2 = 0.0f;
    for (int c = 0; c < NCLS; c++) {
        int cnt = g_counts[c];
        if (cnt > 0) {
            float cnt3 = 3.0f * (float)cnt;
            float s    = g_seg[c * DIM + d];
            float mix  = s / cnt3;
            float lm   = __logf(fmaxf(mix, EPSF));
            t2 += s * lm / cnt3;
        }
    }
    red[d] = t2;
    __syncthreads();
    for (int o = 128; o; o >>= 1) {
        if (d < o) red[d] += red[d + o];
        __syncthreads();
    }
    if (d == 0) {
        float t1 = 0.0f;
        for (int i = 0; i < 64; i++) t1 += g_t1[i];
        float loss = (t1 - red[0]) / (float)DIM;
        out[0] = LOSSW * loss;
    }
}

// ---------------- launch ----------------
extern "C" void kernel_launch(void* const* d_in, const int* in_sizes, int n_in,
                              void* d_out, int out_size) {
    const float* x0  = (const float*)d_in[0];
    const float* x1  = (const float*)d_in[1];
    const float* x2  = (const float*)d_in[2];
    const int*   lab = (const int*)d_in[3];
    int N = in_sizes[3];
    if (N > NMAX) N = NMAX;

    int nb512 = (N + 511) / 512;
    k_zero<<<96, 256>>>();
    k_hist<<<nb512, 512>>>(lab, N);
    k_prefix<<<1, 32>>>();
    k_scatter<<<nb512, 512>>>(lab, N);

    int warps  = (N + JPW - 1) / JPW;
    int blocks = (warps + 7) / 8;
    k_main<<<blocks, 256>>>(x0, x1, x2, N);

    k_final<<<1, 256>>>((float*)d_out);
}

// round 7
// speedup vs baseline: 1.6119x; 1.0866x over previous
#include <cuda_runtime.h>

#define NCLS 80
#define DIM 256
#define NMAX 65536
#define EPSF 1e-7f
#define LOSSW 0.01f
#define JPW 8   // sorted entries per warp

// ---------------- device scratch (no allocations allowed) ----------------
__device__ float g_seg[NCLS * DIM];   // class segment sums over all 3N rows
__device__ int   g_counts[NCLS];
__device__ int   g_cursor[NCLS];
__device__ int   g_sorted[NMAX];      // packed: (class<<20) | row_index
__device__ float g_t1[64];            // partial accumulators for term1

__device__ __forceinline__ int clampc(int c) {
    return (c < 0) ? 0 : (c >= NCLS ? NCLS - 1 : c);
}

// x*ln(x) via MUFU.LG2; exact 0 at x==0.
__device__ __forceinline__ float xlnxf(float x) {
    float l = __logf(x);
    return (x > 0.0f) ? x * l : 0.0f;
}

// ---------------- K0: zero scratch ----------------
__global__ void k_zero() {
    int i = blockIdx.x * blockDim.x + threadIdx.x;
    for (int k = i; k < NCLS * DIM; k += gridDim.x * blockDim.x) g_seg[k] = 0.0f;
    if (i < NCLS) g_counts[i] = 0;
    if (i < 64)   g_t1[i] = 0.0f;
}

// ---------------- K1: histogram, block-aggregated ----------------
__global__ void k_hist(const int* __restrict__ labels, int N) {
    __shared__ int h[NCLS];
    for (int c = threadIdx.x; c < NCLS; c += blockDim.x) h[c] = 0;
    __syncthreads();
    int i = blockIdx.x * blockDim.x + threadIdx.x;
    if (i < N) atomicAdd(&h[clampc(labels[i])], 1);
    __syncthreads();
    for (int c = threadIdx.x; c < NCLS; c += blockDim.x)
        if (h[c]) atomicAdd(&g_counts[c], h[c]);
}

// ---------------- K2: exclusive prefix -> cursors ----------------
__global__ void k_prefix() {
    if (threadIdx.x == 0) {
        int run = 0;
        for (int c = 0; c < NCLS; c++) {
            g_cursor[c] = run;
            run += g_counts[c];
        }
    }
}

// ---------------- K3: counting-sort scatter, block-aggregated ----------------
__global__ void k_scatter(const int* __restrict__ labels, int N) {
    __shared__ int h[NCLS];     // block count, then reused as local cursor
    __shared__ int base[NCLS];  // global base for this block's slice
    int tid = threadIdx.x;
    for (int c = tid; c < NCLS; c += blockDim.x) h[c] = 0;
    __syncthreads();
    int i = blockIdx.x * blockDim.x + tid;
    int c = -1;
    if (i < N) {
        c = clampc(labels[i]);
        atomicAdd(&h[c], 1);
    }
    __syncthreads();
    for (int cc = tid; cc < NCLS; cc += blockDim.x) {
        int cnt = h[cc];
        base[cc] = cnt ? atomicAdd(&g_cursor[cc], cnt) : 0;
        h[cc] = 0;
    }
    __syncthreads();
    if (i < N) {
        int loc = atomicAdd(&h[c], 1);
        int p = base[c] + loc;
        if (p >= 0 && p < NMAX) g_sorted[p] = (c << 20) | i;
    }
}

// ---------------- K4: fused single-pass main kernel ----------------
// One warp handles JPW sorted entries (3 rows each). Lane owns 8 columns.
// ONLY s2 (the norm) is warp-reduced per row (5 shfls); the xlogy term is
// accumulated per-lane and reduced once per warp at the end. Class segment
// accumulators live in registers, flushed to g_seg on class change.
__global__ void k_main(const float* __restrict__ x0, const float* __restrict__ x1,
                       const float* __restrict__ x2, int N) {
    int gwarp = (blockIdx.x * blockDim.x + threadIdx.x) >> 5;
    int lane  = threadIdx.x & 31;
    int pos0  = gwarp * JPW;
    if (pos0 >= N) return;
    int pend = min(pos0 + JPW, N);

    float acc[8];
#pragma unroll
    for (int k = 0; k < 8; k++) acc[k] = 0.0f;
    int   curc = -1;
    float ic3  = 0.0f;         // 1 / (3 * count[c])
    float t1l  = 0.0f;         // per-lane partial of term1

    for (int pos = pos0; pos < pend; pos++) {
        int v = g_sorted[pos];
        int j = v & 0xFFFFF;
        int c = v >> 20;

        // Issue all 6 loads (3 matrices x 2 float4) before any compute.
        size_t off = (size_t)j * DIM;
        const float4* r0 = (const float4*)(x0 + off);
        const float4* r1 = (const float4*)(x1 + off);
        const float4* r2 = (const float4*)(x2 + off);
        float4 A[3], B[3];
        A[0] = r0[lane]; B[0] = r0[32 + lane];
        A[1] = r1[lane]; B[1] = r1[32 + lane];
        A[2] = r2[lane]; B[2] = r2[32 + lane];

        if (c != curc) {
            if (curc >= 0) {
#pragma unroll
                for (int k = 0; k < 4; k++) {
                    atomicAdd(&g_seg[curc * DIM + lane * 4 + k],       acc[k]);
                    atomicAdd(&g_seg[curc * DIM + 128 + lane * 4 + k], acc[4 + k]);
                    acc[k] = 0.0f;
                    acc[4 + k] = 0.0f;
                }
            }
            curc = c;
            ic3  = 1.0f / (3.0f * (float)g_counts[c]);
        }

#pragma unroll
        for (int mm = 0; mm < 3; mm++) {
            float4 a = A[mm];
            float4 b = B[mm];

            // Per-lane partials (no warp reduction needed for s1/sxl).
            float s1l = ((a.x + a.y) + (a.z + a.w)) + ((b.x + b.y) + (b.z + b.w));
            float s2  = fmaf(a.x, a.x, fmaf(a.y, a.y, fmaf(a.z, a.z, a.w * a.w)));
            s2 = fmaf(b.x, b.x, fmaf(b.y, b.y, fmaf(b.z, b.z, fmaf(b.w, b.w, s2))));
            float sxl = ((xlnxf(a.x) + xlnxf(a.y)) + (xlnxf(a.z) + xlnxf(a.w)))
                      + ((xlnxf(b.x) + xlnxf(b.y)) + (xlnxf(b.z) + xlnxf(b.w)));

            // Only the norm needs an immediate warp reduction (for w broadcast).
#pragma unroll
            for (int o = 16; o; o >>= 1)
                s2 += __shfl_xor_sync(0xffffffffu, s2, o);

            s2 = fmaxf(s2, 1e-24f);            // denom = sqrt(s2) >= 1e-12
            float w   = rsqrtf(s2);            // 1/denom
            float lnd = 0.5f * __logf(s2);     // ln(denom)
            float wic = w * ic3;
            // per-lane contribution: w*(sxl_l - lnd*s1_l)/counts3
            t1l = fmaf(wic, fmaf(-lnd, s1l, sxl), t1l);

            acc[0] = fmaf(a.x, w, acc[0]);
            acc[1] = fmaf(a.y, w, acc[1]);
            acc[2] = fmaf(a.z, w, acc[2]);
            acc[3] = fmaf(a.w, w, acc[3]);
            acc[4] = fmaf(b.x, w, acc[4]);
            acc[5] = fmaf(b.y, w, acc[5]);
            acc[6] = fmaf(b.z, w, acc[6]);
            acc[7] = fmaf(b.w, w, acc[7]);
        }
    }
    if (curc >= 0) {
#pragma unroll
        for (int k = 0; k < 4; k++) {
            atomicAdd(&g_seg[curc * DIM + lane * 4 + k],       acc[k]);
            atomicAdd(&g_seg[curc * DIM + 128 + lane * 4 + k], acc[4 + k]);
        }
    }
    // One warp-reduction of the per-lane term1 partials, then one atomic.
#pragma unroll
    for (int o = 16; o; o >>= 1)
        t1l += __shfl_xor_sync(0xffffffffu, t1l, o);
    if (lane == 0) atomicAdd(&g_t1[gwarp & 63], t1l);
}

// ---------------- K5: finalize (tiny: 80*256 elements) ----------------
__global__ void k_final(float* __restrict__ out) {
    __shared__ float red[256];
    int d = threadIdx.x;
    float t2 = 0.0f;
    for (int c = 0; c < NCLS; c++) {
        int cnt = g_counts[c];
        if (cnt > 0) {
            float cnt3 = 3.0f * (float)cnt;
            float s    = g_seg[c * DIM + d];
            float mix  = s / cnt3;
            float lm   = __logf(fmaxf(mix, EPSF));
            t2 += s * lm / cnt3;
        }
    }
    red[d] = t2;
    __syncthreads();
    for (int o = 128; o; o >>= 1) {
        if (d < o) red[d] += red[d + o];
        __syncthreads();
    }
    if (d == 0) {
        float t1 = 0.0f;
        for (int i = 0; i < 64; i++) t1 += g_t1[i];
        float loss = (t1 - red[0]) / (float)DIM;
        out[0] = LOSSW * loss;
    }
}

// ---------------- launch ----------------
extern "C" void kernel_launch(void* const* d_in, const int* in_sizes, int n_in,
                              void* d_out, int out_size) {
    const float* x0  = (const float*)d_in[0];
    const float* x1  = (const float*)d_in[1];
    const float* x2  = (const float*)d_in[2];
    const int*   lab = (const int*)d_in[3];
    int N = in_sizes[3];
    if (N > NMAX) N = NMAX;

    int nb512 = (N + 511) / 512;
    k_zero<<<96, 256>>>();
    k_hist<<<nb512, 512>>>(lab, N);
    k_prefix<<<1, 32>>>();
    k_scatter<<<nb512, 512>>>(lab, N);

    int warps  = (N + JPW - 1) / JPW;
    int blocks = (warps + 7) / 8;
    k_main<<<blocks, 256>>>(x0, x1, x2, N);

    k_final<<<1, 256>>>((float*)d_out);
}

// round 8
// speedup vs baseline: 1.6570x; 1.0280x over previous
#include <cuda_runtime.h>

#define NCLS 80
#define DIM 256
#define NMAX 65536
#define CAP 1024          // per-class bucket capacity (mean 819, +7 sigma)
#define EPSF 1e-7f
#define LOSSW 0.01f
#define JPW 8             // entries per warp
#define WPC (CAP / JPW)   // warps per class = 128

// ---------------- device scratch (no allocations allowed) ----------------
__device__ float g_seg[NCLS * DIM];      // class segment sums
__device__ int   g_counts[NCLS];         // cursor during bucket, count after
__device__ int   g_bucket[NCLS * CAP];   // per-class row indices
__device__ float g_t1[64];               // partial accumulators for term1

__device__ __forceinline__ int clampc(int c) {
    return (c < 0) ? 0 : (c >= NCLS ? NCLS - 1 : c);
}

// x*ln(x) via MUFU.LG2; exact 0 at x==0.
__device__ __forceinline__ float xlnxf(float x) {
    float l = __logf(x);
    return (x > 0.0f) ? x * l : 0.0f;
}

// ---------------- K0: zero scratch ----------------
__global__ void k_zero() {
    int i = blockIdx.x * blockDim.x + threadIdx.x;
    for (int k = i; k < NCLS * DIM; k += gridDim.x * blockDim.x) g_seg[k] = 0.0f;
    if (i < NCLS) g_counts[i] = 0;
    if (i < 64)   g_t1[i] = 0.0f;
}

// ---------------- K1: fused histogram + bucket scatter ----------------
// Block-aggregated: smem histogram, ONE global atomic per (block,class)
// reserves a slice of the class bucket; smem cursor places elements.
// g_counts ends as the true per-class count.
__global__ void k_bucket(const int* __restrict__ labels, int N) {
    __shared__ int h[NCLS];     // block count, then local cursor
    __shared__ int base[NCLS];  // reserved global base per class
    int tid = threadIdx.x;
    for (int c = tid; c < NCLS; c += blockDim.x) h[c] = 0;
    __syncthreads();
    int i = blockIdx.x * blockDim.x + tid;
    int c = -1;
    if (i < N) {
        c = clampc(labels[i]);
        atomicAdd(&h[c], 1);
    }
    __syncthreads();
    for (int cc = tid; cc < NCLS; cc += blockDim.x) {
        int cnt = h[cc];
        base[cc] = cnt ? atomicAdd(&g_counts[cc], cnt) : 0;
        h[cc] = 0;
    }
    __syncthreads();
    if (i < N) {
        int p = base[c] + atomicAdd(&h[c], 1);
        if (p < CAP) g_bucket[c * CAP + p] = i;
    }
}

// ---------------- K2: fused single-pass main kernel ----------------
// warp = (class, chunk): all entries of a warp share one class -> the hot
// loop has NO class branch, so iterations software-pipeline cleanly.
// Lane owns 8 columns (two float4 per matrix). Only the norm is
// warp-reduced per row; term1 stays per-lane until the end.
__global__ void __launch_bounds__(256) k_main(
        const float* __restrict__ x0, const float* __restrict__ x1,
        const float* __restrict__ x2) {
    int gwarp = (blockIdx.x * blockDim.x + threadIdx.x) >> 5;
    int lane  = threadIdx.x & 31;
    int c     = gwarp / WPC;
    int chunk = gwarp % WPC;
    if (c >= NCLS) return;

    int count = g_counts[c];
    int pos0  = chunk * JPW;
    if (pos0 >= count) return;
    int pend = min(pos0 + JPW, min(count, CAP));
    float ic3 = 1.0f / (3.0f * (float)count);

    float acc[8];
#pragma unroll
    for (int k = 0; k < 8; k++) acc[k] = 0.0f;
    float t1l = 0.0f;

    for (int pos = pos0; pos < pend; pos++) {
        int j = g_bucket[c * CAP + pos];

        size_t off = (size_t)j * DIM;
        const float4* r0 = (const float4*)(x0 + off);
        const float4* r1 = (const float4*)(x1 + off);
        const float4* r2 = (const float4*)(x2 + off);
        float4 A[3], B[3];
        A[0] = __ldcs(r0 + lane); B[0] = __ldcs(r0 + 32 + lane);
        A[1] = __ldcs(r1 + lane); B[1] = __ldcs(r1 + 32 + lane);
        A[2] = __ldcs(r2 + lane); B[2] = __ldcs(r2 + 32 + lane);

#pragma unroll
        for (int mm = 0; mm < 3; mm++) {
            float4 a = A[mm];
            float4 b = B[mm];

            float s1l = ((a.x + a.y) + (a.z + a.w)) + ((b.x + b.y) + (b.z + b.w));
            float s2  = fmaf(a.x, a.x, fmaf(a.y, a.y, fmaf(a.z, a.z, a.w * a.w)));
            s2 = fmaf(b.x, b.x, fmaf(b.y, b.y, fmaf(b.z, b.z, fmaf(b.w, b.w, s2))));
            float sxl = ((xlnxf(a.x) + xlnxf(a.y)) + (xlnxf(a.z) + xlnxf(a.w)))
                      + ((xlnxf(b.x) + xlnxf(b.y)) + (xlnxf(b.z) + xlnxf(b.w)));

#pragma unroll
            for (int o = 16; o; o >>= 1)
                s2 += __shfl_xor_sync(0xffffffffu, s2, o);

            s2 = fmaxf(s2, 1e-24f);            // denom = sqrt(s2) >= 1e-12
            float w   = rsqrtf(s2);            // 1/denom
            float lnd = 0.5f * __logf(s2);     // ln(denom)
            float wic = w * ic3;
            t1l = fmaf(wic, fmaf(-lnd, s1l, sxl), t1l);

            acc[0] = fmaf(a.x, w, acc[0]);
            acc[1] = fmaf(a.y, w, acc[1]);
            acc[2] = fmaf(a.z, w, acc[2]);
            acc[3] = fmaf(a.w, w, acc[3]);
            acc[4] = fmaf(b.x, w, acc[4]);
            acc[5] = fmaf(b.y, w, acc[5]);
            acc[6] = fmaf(b.z, w, acc[6]);
            acc[7] = fmaf(b.w, w, acc[7]);
        }
    }

    // One flush per warp (class fixed).
#pragma unroll
    for (int k = 0; k < 4; k++) {
        atomicAdd(&g_seg[c * DIM + lane * 4 + k],       acc[k]);
        atomicAdd(&g_seg[c * DIM + 128 + lane * 4 + k], acc[4 + k]);
    }
#pragma unroll
    for (int o = 16; o; o >>= 1)
        t1l += __shfl_xor_sync(0xffffffffu, t1l, o);
    if (lane == 0) atomicAdd(&g_t1[gwarp & 63], t1l);
}

// ---------------- K3: finalize (tiny: 80*256 elements) ----------------
__global__ void k_final(float* __restrict__ out) {
    __shared__ float red[256];
    int d = threadIdx.x;
    float t2 = 0.0f;
    for (int c = 0; c < NCLS; c++) {
        int cnt = g_counts[c];
        if (cnt > 0) {
            float cnt3 = 3.0f * (float)cnt;
            float s    = g_seg[c * DIM + d];
            float mix  = s / cnt3;
            float lm   = __logf(fmaxf(mix, EPSF));
            t2 += s * lm / cnt3;
        }
    }
    red[d] = t2;
    __syncthreads();
    for (int o = 128; o; o >>= 1) {
        if (d < o) red[d] += red[d + o];
        __syncthreads();
    }
    if (d == 0) {
        float t1 = 0.0f;
        for (int i = 0; i < 64; i++) t1 += g_t1[i];
        float loss = (t1 - red[0]) / (float)DIM;
        out[0] = LOSSW * loss;
    }
}

// ---------------- launch ----------------
extern "C" void kernel_launch(void* const* d_in, const int* in_sizes, int n_in,
                              void* d_out, int out_size) {
    const float* x0  = (const float*)d_in[0];
    const float* x1  = (const float*)d_in[1];
    const float* x2  = (const float*)d_in[2];
    const int*   lab = (const int*)d_in[3];
    int N = in_sizes[3];
    if (N > NMAX) N = NMAX;

    k_zero<<<96, 256>>>();
    k_bucket<<<(N + 511) / 512, 512>>>(lab, N);

    // 80 classes x 128 warps-per-class = 10240 warps = 1280 blocks of 256.
    k_main<<<NCLS * WPC / 8, 256>>>(x0, x1, x2);

    k_final<<<1, 256>>>((float*)d_out);
}

// round 9
// speedup vs baseline: 2.5418x; 1.5340x over previous
#include <cuda_runtime.h>

#define NCLS 80
#define DIM 256
#define NMAX 65536
#define CAP 1024          // per-class bucket capacity (mean 819, +7 sigma)
#define EPSF 1e-7f
#define LOSSW 0.01f
#define JPW 8             // entries per warp
#define WPC (CAP / JPW)   // warps per class = 128

// ---------------- device scratch (no allocations allowed) ----------------
__device__ float g_seg[NCLS * DIM];      // class segment sums
__device__ int   g_counts[NCLS];         // cursor during bucket, count after
__device__ int   g_bucket[NCLS * CAP];   // per-class row indices
__device__ float g_t1[64];               // partial accumulators for term1
__device__ float g_t2;                   // accumulated term2

__device__ __forceinline__ int clampc(int c) {
    return (c < 0) ? 0 : (c >= NCLS ? NCLS - 1 : c);
}

// x*ln(x) via MUFU.LG2; exact 0 at x==0.
__device__ __forceinline__ float xlnxf(float x) {
    float l = __logf(x);
    return (x > 0.0f) ? x * l : 0.0f;
}

// ---------------- K0: zero scratch ----------------
__global__ void k_zero() {
    int i = blockIdx.x * blockDim.x + threadIdx.x;
    for (int k = i; k < NCLS * DIM; k += gridDim.x * blockDim.x) g_seg[k] = 0.0f;
    if (i < NCLS) g_counts[i] = 0;
    if (i < 64)   g_t1[i] = 0.0f;
    if (i == 64)  g_t2 = 0.0f;
}

// ---------------- K1: fused histogram + bucket scatter ----------------
__global__ void k_bucket(const int* __restrict__ labels, int N) {
    __shared__ int h[NCLS];     // block count, then local cursor
    __shared__ int base[NCLS];  // reserved global base per class
    int tid = threadIdx.x;
    for (int c = tid; c < NCLS; c += blockDim.x) h[c] = 0;
    __syncthreads();
    int i = blockIdx.x * blockDim.x + tid;
    int c = -1;
    if (i < N) {
        c = clampc(labels[i]);
        atomicAdd(&h[c], 1);
    }
    __syncthreads();
    for (int cc = tid; cc < NCLS; cc += blockDim.x) {
        int cnt = h[cc];
        base[cc] = cnt ? atomicAdd(&g_counts[cc], cnt) : 0;
        h[cc] = 0;
    }
    __syncthreads();
    if (i < N) {
        int p = base[c] + atomicAdd(&h[c], 1);
        if (p < CAP) g_bucket[c * CAP + p] = i;
    }
}

// ---------------- K2: fused single-pass main kernel ----------------
// warp = (class, chunk): branch-free hot loop; lane owns 8 columns.
// Only the norm is warp-reduced per row; term1 stays per-lane to the end.
__global__ void __launch_bounds__(256) k_main(
        const float* __restrict__ x0, const float* __restrict__ x1,
        const float* __restrict__ x2) {
    int gwarp = (blockIdx.x * blockDim.x + threadIdx.x) >> 5;
    int lane  = threadIdx.x & 31;
    int c     = gwarp / WPC;
    int chunk = gwarp % WPC;
    if (c >= NCLS) return;

    int count = g_counts[c];
    int pos0  = chunk * JPW;
    if (pos0 >= count) return;
    int pend = min(pos0 + JPW, min(count, CAP));
    float ic3 = 1.0f / (3.0f * (float)count);

    float acc[8];
#pragma unroll
    for (int k = 0; k < 8; k++) acc[k] = 0.0f;
    float t1l = 0.0f;

    for (int pos = pos0; pos < pend; pos++) {
        int j = g_bucket[c * CAP + pos];

        size_t off = (size_t)j * DIM;
        const float4* r0 = (const float4*)(x0 + off);
        const float4* r1 = (const float4*)(x1 + off);
        const float4* r2 = (const float4*)(x2 + off);
        float4 A[3], B[3];
        A[0] = __ldcs(r0 + lane); B[0] = __ldcs(r0 + 32 + lane);
        A[1] = __ldcs(r1 + lane); B[1] = __ldcs(r1 + 32 + lane);
        A[2] = __ldcs(r2 + lane); B[2] = __ldcs(r2 + 32 + lane);

#pragma unroll
        for (int mm = 0; mm < 3; mm++) {
            float4 a = A[mm];
            float4 b = B[mm];

            float s1l = ((a.x + a.y) + (a.z + a.w)) + ((b.x + b.y) + (b.z + b.w));
            float s2  = fmaf(a.x, a.x, fmaf(a.y, a.y, fmaf(a.z, a.z, a.w * a.w)));
            s2 = fmaf(b.x, b.x, fmaf(b.y, b.y, fmaf(b.z, b.z, fmaf(b.w, b.w, s2))));
            float sxl = ((xlnxf(a.x) + xlnxf(a.y)) + (xlnxf(a.z) + xlnxf(a.w)))
                      + ((xlnxf(b.x) + xlnxf(b.y)) + (xlnxf(b.z) + xlnxf(b.w)));

#pragma unroll
            for (int o = 16; o; o >>= 1)
                s2 += __shfl_xor_sync(0xffffffffu, s2, o);

            s2 = fmaxf(s2, 1e-24f);            // denom = sqrt(s2) >= 1e-12
            float w   = rsqrtf(s2);            // 1/denom
            float lnd = 0.5f * __logf(s2);     // ln(denom)
            float wic = w * ic3;
            t1l = fmaf(wic, fmaf(-lnd, s1l, sxl), t1l);

            acc[0] = fmaf(a.x, w, acc[0]);
            acc[1] = fmaf(a.y, w, acc[1]);
            acc[2] = fmaf(a.z, w, acc[2]);
            acc[3] = fmaf(a.w, w, acc[3]);
            acc[4] = fmaf(b.x, w, acc[4]);
            acc[5] = fmaf(b.y, w, acc[5]);
            acc[6] = fmaf(b.z, w, acc[6]);
            acc[7] = fmaf(b.w, w, acc[7]);
        }
    }

    // One flush per warp (class fixed).
#pragma unroll
    for (int k = 0; k < 4; k++) {
        atomicAdd(&g_seg[c * DIM + lane * 4 + k],       acc[k]);
        atomicAdd(&g_seg[c * DIM + 128 + lane * 4 + k], acc[4 + k]);
    }
#pragma unroll
    for (int o = 16; o; o >>= 1)
        t1l += __shfl_xor_sync(0xffffffffu, t1l, o);
    if (lane == 0) atomicAdd(&g_t1[gwarp & 63], t1l);
}

// ---------------- K3: parallel finalize: one block per class ----------------
// 80 blocks x 256 threads: all 20480 g_seg loads issue in parallel
// (the old single-block serial loop was 52us of exposed latency).
__global__ void k_final(float* __restrict__ out) {
    __shared__ float red[256];
    int c = blockIdx.x;
    int d = threadIdx.x;
    int cnt = g_counts[c];
    float t2 = 0.0f;
    if (cnt > 0) {
        float icnt3 = 1.0f / (3.0f * (float)cnt);
        float s     = g_seg[c * DIM + d];
        float mix   = s * icnt3;
        float lm    = __logf(fmaxf(mix, EPSF));
        t2 = s * lm * icnt3;
    }
    red[d] = t2;
    __syncthreads();
    for (int o = 128; o; o >>= 1) {
        if (d < o) red[d] += red[d + o];
        __syncthreads();
    }
    if (d == 0) atomicAdd(&g_t2, red[0]);
}

// ---------------- K4: combine partials, write scalar output ----------------
__global__ void k_out(float* __restrict__ out) {
    int lane = threadIdx.x;           // 64 threads
    float t1 = g_t1[lane];
    __syncthreads();
#pragma unroll
    for (int o = 16; o; o >>= 1)
        t1 += __shfl_xor_sync(0xffffffffu, t1, o);
    __shared__ float w0;
    if (lane == 32) w0 = t1;          // warp1 lane0 writes
    __syncthreads();
    if (lane == 0) {
        float tt = t1 + w0;
        float loss = (tt - g_t2) / (float)DIM;
        out[0] = LOSSW * loss;
    }
}

// ---------------- launch ----------------
extern "C" void kernel_launch(void* const* d_in, const int* in_sizes, int n_in,
                              void* d_out, int out_size) {
    const float* x0  = (const float*)d_in[0];
    const float* x1  = (const float*)d_in[1];
    const float* x2  = (const float*)d_in[2];
    const int*   lab = (const int*)d_in[3];
    int N = in_sizes[3];
    if (N > NMAX) N = NMAX;

    k_zero<<<96, 256>>>();
    k_bucket<<<(N + 511) / 512, 512>>>(lab, N);

    // 80 classes x 128 warps-per-class = 10240 warps = 1280 blocks of 256.
    k_main<<<NCLS * WPC / 8, 256>>>(x0, x1, x2);

    k_final<<<NCLS, 256>>>((float*)d_out);
    k_out<<<1, 64>>>((float*)d_out);
}